// round 12
// baseline (speedup 1.0000x reference)
#include <cuda_runtime.h>
#include <cuda_fp16.h>
#include <cstdint>

#define B_SZ    16384
#define NSTATES 4096
#define GTOT    768
#define NACT    4

// ---------------- packed fp32x2 helpers (sm_103 FFMA2 pipe) -----------------
#define FMA_F32X2(d, a, b, c) \
    asm("fma.rn.f32x2 %0, %1, %2, %3;" : "=l"(d) : "l"(a), "l"(b), "l"(c))
#define DUP_F32X2(d, s) \
    asm("mov.b64 %0, {%1, %1};" : "=l"(d) : "f"(s))
__device__ __forceinline__ float f32x2_lo(unsigned long long v) {
    return __uint_as_float((unsigned)(v & 0xffffffffull));
}
__device__ __forceinline__ float f32x2_hi(unsigned long long v) {
    return __uint_as_float((unsigned)(v >> 32));
}

// ---------------- mma / ldmatrix / cp.async helpers -------------------------
__device__ __forceinline__ uint32_t smem_to_u32(const void* p) {
    uint32_t a;
    asm("{ .reg .u64 t; cvta.to.shared.u64 t, %1; cvt.u32.u64 %0, t; }" : "=r"(a) : "l"(p));
    return a;
}
#define CP_ASYNC16(dst, src) \
    asm volatile("cp.async.cg.shared.global [%0], [%1], 16;" :: "r"(dst), "l"(src))
#define CP_COMMIT() asm volatile("cp.async.commit_group;" ::: "memory")
#define CP_WAIT(n)  asm volatile("cp.async.wait_group %0;" :: "n"(n) : "memory")

#define LDSM_X4(r0, r1, r2, r3, a) \
    asm volatile("ldmatrix.sync.aligned.m8n8.x4.shared.b16 {%0,%1,%2,%3}, [%4];" \
        : "=r"(r0), "=r"(r1), "=r"(r2), "=r"(r3) : "r"(a))

#define MMA16816(d, a, b0v, b1v) \
    asm volatile("mma.sync.aligned.m16n8k16.row.col.f32.f16.f16.f32 " \
        "{%0,%1,%2,%3}, {%4,%5,%6,%7}, {%8,%9}, {%0,%1,%2,%3};" \
        : "+f"((d)[0]), "+f"((d)[1]), "+f"((d)[2]), "+f"((d)[3]) \
        : "r"((a)[0]), "r"((a)[1]), "r"((a)[2]), "r"((a)[3]), "r"(b0v), "r"(b1v))

// ---------------- device scratch --------------------------------------------
__device__ int d_off[NACT + 1];
__device__ int d_perm[B_SZ];
__device__ float d_gscratch[(size_t)B_SZ * GTOT];
__device__ __half d_Ah[(size_t)B_SZ * GTOT];      // g_next in fp16
__device__ __half d_Wh[(size_t)NSTATES * GTOT];   // W in fp16

// ---------------- fused single-block counting sort --------------------------
__global__ void k_sort(const int* __restrict__ act) {
    __shared__ int cnt[NACT];
    __shared__ int cur[NACT];
    const int t = threadIdx.x;
    const int lane = t & 31;
    if (t < NACT) cnt[t] = 0;
    __syncthreads();
    for (int i = t; i < B_SZ; i += blockDim.x) {
        int a = act[i];
        unsigned mask = __match_any_sync(0xffffffffu, a);
        if (lane == (__ffs(mask) - 1)) atomicAdd(&cnt[a], __popc(mask));
    }
    __syncthreads();
    if (t == 0) {
        int s = 0;
        for (int a = 0; a < NACT; a++) { d_off[a] = s; cur[a] = s; s += cnt[a]; }
        d_off[NACT] = s;
    }
    __syncthreads();
    for (int i = t; i < B_SZ; i += blockDim.x) {
        int a = act[i];
        unsigned mask = __match_any_sync(0xffffffffu, a);
        int leader = __ffs(mask) - 1;
        int rank = __popc(mask & ((1u << lane) - 1u));
        int base = 0;
        if (lane == leader) base = atomicAdd(&cur[a], __popc(mask));
        base = __shfl_sync(0xffffffffu, base, leader);
        d_perm[base + rank] = i;
    }
}

// ---------------- W -> fp16 --------------------------------------------------
__global__ void k_wsplit(const float* __restrict__ W) {
    int i = blockIdx.x * blockDim.x + threadIdx.x;
    float4 w4 = ((const float4*)W)[i];
    ((__half2*)d_Wh)[2 * i]     = __floats2half2_rn(w4.x, w4.y);
    ((__half2*)d_Wh)[2 * i + 1] = __floats2half2_rn(w4.z, w4.w);
}

// ---------------- transition: per-action GEMM + clip + fp16 cast ------------
__global__ void __launch_bounds__(256)
k_transition(const int* __restrict__ csi,
             const float* __restrict__ emb,
             const float* __restrict__ D0, const float* __restrict__ D1,
             const float* __restrict__ D2, const float* __restrict__ D3,
             float* __restrict__ gout)
{
    const int jt = blockIdx.y;
    const int a  = blockIdx.z;
    int jbase, moff, nf; const float* D;
    if (jt < 4)       { jbase = jt * 64;        moff = 0;   nf = 256; D = D0; }
    else if (jt < 8)  { jbase = (jt - 4) * 64;  moff = 256; nf = 256; D = D1; }
    else if (jt < 10) { jbase = (jt - 8) * 64;  moff = 512; nf = 128; D = D2; }
    else              { jbase = (jt - 10) * 64; moff = 640; nf = 128; D = D3; }

    const int row0   = d_off[a] + blockIdx.x * 128;
    const int rowEnd = d_off[a + 1];
    if (row0 >= rowEnd) return;
    const float* __restrict__ Da = D + (size_t)a * nf * nf;

    __shared__ int   permS[128];
    __shared__ int   stateS[128];
    __shared__ float gsm[32][132];
    __shared__ float dsm[32][68];

    const int t = threadIdx.x;
    if (t < 128) {
        int r = row0 + t;
        if (r < rowEnd) { int b = d_perm[r]; permS[t] = b; stateS[t] = csi[b]; }
        else            { permS[t] = -1;     stateS[t] = 0; }
    }
    __syncthreads();

    unsigned long long acc2[8][2];
    #pragma unroll
    for (int i = 0; i < 8; i++) { acc2[i][0] = 0ull; acc2[i][1] = 0ull; }
    const int rs = (t >> 4) * 8;   // 0..120
    const int cs = (t & 15) * 4;   // 0..60

    for (int k0 = 0; k0 < nf; k0 += 32) {
        #pragma unroll
        for (int q = 0; q < 4; q++) {        // gsm: 128 rows x 32 k
            int id = t * 4 + q;
            int r  = id >> 3;
            int v  = (id & 7) * 4;
            float4 g4 = *(const float4*)(emb + (size_t)stateS[r] * GTOT + moff + k0 + v);
            gsm[v + 0][r] = g4.x; gsm[v + 1][r] = g4.y;
            gsm[v + 2][r] = g4.z; gsm[v + 3][r] = g4.w;
        }
        #pragma unroll
        for (int q = 0; q < 2; q++) {        // dsm: 64 rows x 32 k
            int id = t * 2 + q;
            int r  = id >> 3;
            int v  = (id & 7) * 4;
            float4 dd = *(const float4*)(Da + (size_t)(jbase + r) * nf + k0 + v);
            dsm[v + 0][r] = dd.x; dsm[v + 1][r] = dd.y;
            dsm[v + 2][r] = dd.z; dsm[v + 3][r] = dd.w;
        }
        __syncthreads();
        #pragma unroll
        for (int kk = 0; kk < 32; kk++) {
            const unsigned long long* bp = (const unsigned long long*)&dsm[kk][cs];
            unsigned long long b0 = bp[0], b1 = bp[1];
            const float2* ap = (const float2*)&gsm[kk][rs];
            #pragma unroll
            for (int h = 0; h < 4; h++) {
                float2 av = ap[h];
                unsigned long long a0, a1;
                DUP_F32X2(a0, av.x);
                DUP_F32X2(a1, av.y);
                FMA_F32X2(acc2[2 * h][0],     a0, b0, acc2[2 * h][0]);
                FMA_F32X2(acc2[2 * h][1],     a0, b1, acc2[2 * h][1]);
                FMA_F32X2(acc2[2 * h + 1][0], a1, b0, acc2[2 * h + 1][0]);
                FMA_F32X2(acc2[2 * h + 1][1], a1, b1, acc2[2 * h + 1][1]);
            }
        }
        __syncthreads();
    }

    #pragma unroll
    for (int i = 0; i < 8; i++) {
        int rl = rs + i;
        int borig = permS[rl];
        if (borig < 0) continue;
        int col = moff + jbase + cs;
        float4 g4 = *(const float4*)(emb + (size_t)stateS[rl] * GTOT + col);
        float4 o;
        o.x = fminf(fmaxf(g4.x + f32x2_lo(acc2[i][0]), -1.f), 1.f);
        o.y = fminf(fmaxf(g4.y + f32x2_hi(acc2[i][0]), -1.f), 1.f);
        o.z = fminf(fmaxf(g4.z + f32x2_lo(acc2[i][1]), -1.f), 1.f);
        o.w = fminf(fmaxf(g4.w + f32x2_hi(acc2[i][1]), -1.f), 1.f);
        *(float4*)(gout + (size_t)borig * GTOT + col) = o;

        __half2* dh = (__half2*)(d_Ah + (size_t)borig * GTOT + col);
        dh[0] = __floats2half2_rn(o.x, o.y);
        dh[1] = __floats2half2_rn(o.z, o.w);
    }
}

// ---------------- HMMA logits GEMM ------------------------------------------
// C[b,s] = sum_k A[b,k]*Wh[s,k] + bias[s]      (A, W fp16; f32 accum)
// BM=128, BN=256, BK=64; 512 thr / 16 warps (4M x 4N), warp tile 32x64.
// 3-stage cp.async ring, one __syncthreads per K-iter. 1 CTA/SM.
#define GEMM_ITERS 12                        // 768 / 64
#define STG_B      49152                     // A 16K + B 32K
#define OFF_B      16384
#define GSM_TOTAL  (3 * STG_B)               // 144 KB

__device__ __forceinline__ void g_load_stage(int it, int stg, int m0, int n0,
                                             int tid, uint32_t smem_base) {
    const int kc = it * 64;
    const uint32_t sbase = smem_base + stg * STG_B;
    // A: 1024 x 16B ops -> 2 per thread
    #pragma unroll
    for (int q = 0; q < 2; q++) {
        int o   = tid * 2 + q;               // 0..1023
        int row = o >> 3;                    // 0..127
        int ck  = o & 7;
        uint32_t sw = row * 128 + ((ck ^ (row & 7)) << 4);
        CP_ASYNC16(sbase + sw, d_Ah + (size_t)(m0 + row) * GTOT + kc + ck * 8);
    }
    // B: 2048 x 16B ops -> 4 per thread
    #pragma unroll
    for (int q = 0; q < 4; q++) {
        int o   = tid * 4 + q;               // 0..2047
        int row = o >> 3;                    // 0..255
        int ck  = o & 7;
        uint32_t sw = row * 128 + ((ck ^ (row & 7)) << 4);
        CP_ASYNC16(sbase + OFF_B + sw, d_Wh + (size_t)(n0 + row) * GTOT + kc + ck * 8);
    }
}

__global__ void __launch_bounds__(512, 1)
k_logits(const float* __restrict__ bias, float* __restrict__ out)
{
    extern __shared__ char smem[];
    const uint32_t smem_base = smem_to_u32(smem);
    const int tid  = threadIdx.x;
    const int lane = tid & 31;
    const int wid  = tid >> 5;
    const int wm   = wid >> 2;               // 0..3 -> 32 rows each
    const int wn   = wid & 3;                // 0..3 -> 64 cols each
    const int m0 = blockIdx.y * 128;
    const int n0 = blockIdx.x * 256;

    float acc[2][8][4];
    #pragma unroll
    for (int mt = 0; mt < 2; mt++)
        #pragma unroll
        for (int nt = 0; nt < 8; nt++)
            #pragma unroll
            for (int q = 0; q < 4; q++) acc[mt][nt][q] = 0.f;

    const int lr  = lane & 15;               // row within 16-row tile
    const int lk8 = lane >> 4;               // k8 half (0/1)

    g_load_stage(0, 0, m0, n0, tid, smem_base);
    CP_COMMIT();
    g_load_stage(1, 1, m0, n0, tid, smem_base);
    CP_COMMIT();

    for (int it = 0; it < GEMM_ITERS; it++) {
        CP_WAIT(1);
        __syncthreads();

        if (it + 2 < GEMM_ITERS) {
            g_load_stage(it + 2, (it + 2) % 3, m0, n0, tid, smem_base);
            CP_COMMIT();
        }

        const uint32_t sbase = smem_base + (it % 3) * STG_B;
        #pragma unroll
        for (int ks = 0; ks < 4; ks++) {
            const int k8 = ks * 2 + lk8;     // 0..7
            uint32_t afr[2][4], bfr[4][4];
            #pragma unroll
            for (int mt = 0; mt < 2; mt++) {
                int row = wm * 32 + mt * 16 + lr;
                uint32_t ad = sbase + row * 128 + ((k8 ^ (row & 7)) << 4);
                LDSM_X4(afr[mt][0], afr[mt][1], afr[mt][2], afr[mt][3], ad);
            }
            #pragma unroll
            for (int np = 0; np < 4; np++) {
                int rn = wn * 64 + np * 16 + lr;
                uint32_t bd = sbase + OFF_B + rn * 128 + ((k8 ^ (rn & 7)) << 4);
                LDSM_X4(bfr[np][0], bfr[np][1], bfr[np][2], bfr[np][3], bd);
            }
            #pragma unroll
            for (int mt = 0; mt < 2; mt++)
                #pragma unroll
                for (int np = 0; np < 4; np++) {
                    MMA16816(acc[mt][2 * np],     afr[mt], bfr[np][0], bfr[np][2]);
                    MMA16816(acc[mt][2 * np + 1], afr[mt], bfr[np][1], bfr[np][3]);
                }
        }
    }

    // epilogue: float2 stores (32B sectors), bias added
    const int cq = 2 * (lane & 3);
    float2 bv[8];
    #pragma unroll
    for (int nt = 0; nt < 8; nt++)
        bv[nt] = *(const float2*)(bias + n0 + wn * 64 + nt * 8 + cq);

    #pragma unroll
    for (int mt = 0; mt < 2; mt++) {
        int rg = m0 + wm * 32 + mt * 16 + (lane >> 2);
        #pragma unroll
        for (int nt = 0; nt < 8; nt++) {
            float* p = out + (size_t)rg * NSTATES + n0 + wn * 64 + nt * 8 + cq;
            float2 v0 = make_float2(acc[mt][nt][0] + bv[nt].x, acc[mt][nt][1] + bv[nt].y);
            float2 v1 = make_float2(acc[mt][nt][2] + bv[nt].x, acc[mt][nt][3] + bv[nt].y);
            *(float2*)p = v0;
            *(float2*)(p + (size_t)8 * NSTATES) = v1;
        }
    }
}

// ---------------- launch -----------------------------------------------------
extern "C" void kernel_launch(void* const* d_in, const int* in_sizes, int n_in,
                              void* d_out, int out_size)
{
    const int *csi, *ai;
    const float *emb, *W, *bias, *D0, *D1, *D2, *D3;
    if (in_sizes[4] == NSTATES) {
        csi = (const int*)d_in[0]; ai = (const int*)d_in[1];
        emb = (const float*)d_in[2]; W = (const float*)d_in[3];
        bias = (const float*)d_in[4];
        D0 = (const float*)d_in[5]; D1 = (const float*)d_in[6];
        D2 = (const float*)d_in[7]; D3 = (const float*)d_in[8];
    } else {
        csi = (const int*)d_in[0]; ai = (const int*)d_in[1];
        emb = (const float*)d_in[2];
        D0 = (const float*)d_in[3]; D1 = (const float*)d_in[4];
        D2 = (const float*)d_in[5]; D3 = (const float*)d_in[6];
        W = (const float*)d_in[7]; bias = (const float*)d_in[8];
    }

    float* out = (float*)d_out;
    float* gout;
    if ((long long)out_size >= (long long)B_SZ * (NSTATES + GTOT)) {
        gout = out + (size_t)B_SZ * NSTATES;
    } else {
        cudaGetSymbolAddress((void**)&gout, d_gscratch);
    }

    k_sort<<<1, 1024>>>(ai);
    k_wsplit<<<(NSTATES * GTOT / 4) / 256, 256>>>(W);

    dim3 tg(128, 12, NACT);
    k_transition<<<tg, 256>>>(csi, emb, D0, D1, D2, D3, gout);

    cudaFuncSetAttribute(k_logits, cudaFuncAttributeMaxDynamicSharedMemorySize, GSM_TOTAL);
    dim3 gg(NSTATES / 256, B_SZ / 128);
    k_logits<<<gg, 512, GSM_TOTAL>>>(bias, out);
}

// round 13
// speedup vs baseline: 1.7129x; 1.7129x over previous
#include <cuda_runtime.h>
#include <cuda_fp16.h>
#include <cstdint>

#define B_SZ    16384
#define NSTATES 4096
#define GTOT    768
#define NACT    4

// ---------------- mma / ldmatrix / cp.async helpers -------------------------
__device__ __forceinline__ uint32_t smem_to_u32(const void* p) {
    uint32_t a;
    asm("{ .reg .u64 t; cvta.to.shared.u64 t, %1; cvt.u32.u64 %0, t; }" : "=r"(a) : "l"(p));
    return a;
}
#define CP_ASYNC16(dst, src) \
    asm volatile("cp.async.cg.shared.global [%0], [%1], 16;" :: "r"(dst), "l"(src))
#define CP_COMMIT() asm volatile("cp.async.commit_group;" ::: "memory")
#define CP_WAIT(n)  asm volatile("cp.async.wait_group %0;" :: "n"(n) : "memory")

#define LDSM_X4(r0, r1, r2, r3, a) \
    asm volatile("ldmatrix.sync.aligned.m8n8.x4.shared.b16 {%0,%1,%2,%3}, [%4];" \
        : "=r"(r0), "=r"(r1), "=r"(r2), "=r"(r3) : "r"(a))

#define MMA16816(d, a, b0v, b1v) \
    asm volatile("mma.sync.aligned.m16n8k16.row.col.f32.f16.f16.f32 " \
        "{%0,%1,%2,%3}, {%4,%5,%6,%7}, {%8,%9}, {%0,%1,%2,%3};" \
        : "+f"((d)[0]), "+f"((d)[1]), "+f"((d)[2]), "+f"((d)[3]) \
        : "r"((a)[0]), "r"((a)[1]), "r"((a)[2]), "r"((a)[3]), "r"(b0v), "r"(b1v))

// ---------------- device scratch --------------------------------------------
__device__ int d_off[NACT + 1];
__device__ int d_perm[B_SZ];
__device__ float d_gscratch[(size_t)B_SZ * GTOT];
__device__ __half d_Ah[(size_t)B_SZ * GTOT];      // g_next in fp16
__device__ __half d_Wh[(size_t)NSTATES * GTOT];   // W in fp16
__device__ __half d_Eh[(size_t)NSTATES * GTOT];   // emb in fp16
__device__ __half d_D0h[4 * 256 * 256];
__device__ __half d_D1h[4 * 256 * 256];
__device__ __half d_D2h[4 * 128 * 128];
__device__ __half d_D3h[4 * 128 * 128];

// ---------------- fused single-block counting sort --------------------------
__global__ void k_sort(const int* __restrict__ act) {
    __shared__ int cnt[NACT];
    __shared__ int cur[NACT];
    const int t = threadIdx.x;
    const int lane = t & 31;
    if (t < NACT) cnt[t] = 0;
    __syncthreads();
    for (int i = t; i < B_SZ; i += blockDim.x) {
        int a = act[i];
        unsigned mask = __match_any_sync(0xffffffffu, a);
        if (lane == (__ffs(mask) - 1)) atomicAdd(&cnt[a], __popc(mask));
    }
    __syncthreads();
    if (t == 0) {
        int s = 0;
        for (int a = 0; a < NACT; a++) { d_off[a] = s; cur[a] = s; s += cnt[a]; }
        d_off[NACT] = s;
    }
    __syncthreads();
    for (int i = t; i < B_SZ; i += blockDim.x) {
        int a = act[i];
        unsigned mask = __match_any_sync(0xffffffffu, a);
        int leader = __ffs(mask) - 1;
        int rank = __popc(mask & ((1u << lane) - 1u));
        int base = 0;
        if (lane == leader) base = atomicAdd(&cur[a], __popc(mask));
        base = __shfl_sync(0xffffffffu, base, leader);
        d_perm[base + rank] = i;
    }
}

// ---------------- fp32 -> fp16 conversions ----------------------------------
__global__ void k_wsplit(const float* __restrict__ W) {
    int i = blockIdx.x * blockDim.x + threadIdx.x;
    float4 w4 = ((const float4*)W)[i];
    ((__half2*)d_Wh)[2 * i]     = __floats2half2_rn(w4.x, w4.y);
    ((__half2*)d_Wh)[2 * i + 1] = __floats2half2_rn(w4.z, w4.w);
}
__global__ void k_ehalf(const float* __restrict__ E) {
    int i = blockIdx.x * blockDim.x + threadIdx.x;
    float4 w4 = ((const float4*)E)[i];
    ((__half2*)d_Eh)[2 * i]     = __floats2half2_rn(w4.x, w4.y);
    ((__half2*)d_Eh)[2 * i + 1] = __floats2half2_rn(w4.z, w4.w);
}
__global__ void k_dhalf(const float* __restrict__ D0, const float* __restrict__ D1,
                        const float* __restrict__ D2, const float* __restrict__ D3) {
    const int z = blockIdx.z;
    const float* src; __half* dst; int n4;
    switch (z) {
        case 0: src = D0; dst = d_D0h; n4 = 4 * 256 * 256 / 4; break;
        case 1: src = D1; dst = d_D1h; n4 = 4 * 256 * 256 / 4; break;
        case 2: src = D2; dst = d_D2h; n4 = 4 * 128 * 128 / 4; break;
        default: src = D3; dst = d_D3h; n4 = 4 * 128 * 128 / 4; break;
    }
    int i = blockIdx.x * blockDim.x + threadIdx.x;
    if (i < n4) {
        float4 w4 = ((const float4*)src)[i];
        ((__half2*)dst)[2 * i]     = __floats2half2_rn(w4.x, w4.y);
        ((__half2*)dst)[2 * i + 1] = __floats2half2_rn(w4.z, w4.w);
    }
}

// ---------------- HMMA transition -------------------------------------------
// C[r,j] = sum_i Eh[state_r, moff+i] * Dh_a[jbase+j, i]; g_next = clip(g + C)
// Tile: 128 gathered rows x 64 cols, BK=64, 8 warps (warp = 16 rows x 64 cols).
#define TSM_PERM   0
#define TSM_STATE  512
#define TSM_TILES  1024
#define TSTG_B     24576                 // A 16K + B 8K
#define TOFF_B     16384
#define TSM_TOTAL  (TSM_TILES + 2 * TSTG_B)   // 50176

__global__ void __launch_bounds__(256, 2)
k_transition(const int* __restrict__ csi,
             const float* __restrict__ emb,
             float* __restrict__ gout)
{
    extern __shared__ char smem[];
    const uint32_t smem_base = smem_to_u32(smem);
    int* permS   = (int*)(smem + TSM_PERM);
    int* stateS  = (int*)(smem + TSM_STATE);

    const int jt = blockIdx.y;
    const int a  = blockIdx.z;
    int jbase, moff, nf; const __half* Dh;
    if (jt < 4)       { jbase = jt * 64;        moff = 0;   nf = 256; Dh = d_D0h; }
    else if (jt < 8)  { jbase = (jt - 4) * 64;  moff = 256; nf = 256; Dh = d_D1h; }
    else if (jt < 10) { jbase = (jt - 8) * 64;  moff = 512; nf = 128; Dh = d_D2h; }
    else              { jbase = (jt - 10) * 64; moff = 640; nf = 128; Dh = d_D3h; }

    const int row0   = d_off[a] + blockIdx.x * 128;
    const int rowEnd = d_off[a + 1];
    if (row0 >= rowEnd) return;
    const __half* __restrict__ Da = Dh + (size_t)a * nf * nf;

    const int t = threadIdx.x;
    const int lane = t & 31;
    const int wid  = t >> 5;
    if (t < 128) {
        int r = row0 + t;
        if (r < rowEnd) { int b = d_perm[r]; permS[t] = b; stateS[t] = csi[b]; }
        else            { permS[t] = -1;     stateS[t] = 0; }
    }
    __syncthreads();

    const int NK = nf / 64;

    // stage loader: A gathered rows (fp16 emb), B = D rows
    auto load_stage = [&](int kk, int stg) {
        const int kc = kk * 64;
        const uint32_t sbase = smem_base + TSM_TILES + stg * TSTG_B;
        #pragma unroll
        for (int q = 0; q < 4; q++) {       // A: 1024 ops
            int o   = t * 4 + q;
            int row = o >> 3;
            int ck  = o & 7;
            uint32_t sw = row * 128 + ((ck ^ (row & 7)) << 4);
            CP_ASYNC16(sbase + sw, d_Eh + (size_t)stateS[row] * GTOT + moff + kc + ck * 8);
        }
        #pragma unroll
        for (int q = 0; q < 2; q++) {       // B: 512 ops
            int o  = t * 2 + q;
            int rn = o >> 3;
            int ck = o & 7;
            uint32_t sw = rn * 128 + ((ck ^ (rn & 7)) << 4);
            CP_ASYNC16(sbase + TOFF_B + sw, Da + (size_t)(jbase + rn) * nf + kc + ck * 8);
        }
    };

    float acc[8][4];
    #pragma unroll
    for (int nt = 0; nt < 8; nt++)
        #pragma unroll
        for (int q = 0; q < 4; q++) acc[nt][q] = 0.f;

    const int lr  = lane & 15;
    const int lk8 = lane >> 4;

    load_stage(0, 0);
    CP_COMMIT();

    for (int kk = 0; kk < NK; kk++) {
        if (kk + 1 < NK) { load_stage(kk + 1, (kk + 1) & 1); CP_COMMIT(); CP_WAIT(1); }
        else             { CP_WAIT(0); }
        __syncthreads();

        const uint32_t sbase = smem_base + TSM_TILES + (kk & 1) * TSTG_B;
        #pragma unroll
        for (int ks = 0; ks < 4; ks++) {
            const int k8 = ks * 2 + lk8;
            uint32_t afr[4], bfr[4][4];
            int row = wid * 16 + lr;
            uint32_t ad = sbase + row * 128 + ((k8 ^ (row & 7)) << 4);
            LDSM_X4(afr[0], afr[1], afr[2], afr[3], ad);
            #pragma unroll
            for (int np = 0; np < 4; np++) {
                int rn = np * 16 + lr;
                uint32_t bd = sbase + TOFF_B + rn * 128 + ((k8 ^ (rn & 7)) << 4);
                LDSM_X4(bfr[np][0], bfr[np][1], bfr[np][2], bfr[np][3], bd);
            }
            #pragma unroll
            for (int np = 0; np < 4; np++) {
                MMA16816(acc[2 * np],     afr, bfr[np][0], bfr[np][2]);
                MMA16816(acc[2 * np + 1], afr, bfr[np][1], bfr[np][3]);
            }
        }
        __syncthreads();
    }

    // epilogue: residual (fp32 emb) + clip; write gout fp32 + d_Ah fp16
    #pragma unroll
    for (int half = 0; half < 2; half++) {
        int rl = wid * 16 + half * 8 + (lane >> 2);
        int borig = permS[rl];
        if (borig < 0) continue;
        int state = stateS[rl];
        #pragma unroll
        for (int nt = 0; nt < 8; nt++) {
            int col  = jbase + nt * 8 + 2 * (lane & 3);
            int gcol = moff + col;
            float2 g2 = *(const float2*)(emb + (size_t)state * GTOT + gcol);
            float ox = fminf(fmaxf(g2.x + acc[nt][2 * half],     -1.f), 1.f);
            float oy = fminf(fmaxf(g2.y + acc[nt][2 * half + 1], -1.f), 1.f);
            *(float2*)(gout + (size_t)borig * GTOT + gcol) = make_float2(ox, oy);
            *(__half2*)(d_Ah + (size_t)borig * GTOT + gcol) = __floats2half2_rn(ox, oy);
        }
    }
}

// ---------------- HMMA logits GEMM (R8 config: best known) -------------------
// BM=128, BN=128, BK=64; 8 warps (4M x 2N), warp tile 32x64.
// 3-stage cp.async ring, one __syncthreads per K-iter, 2 CTA/SM.
#define GEMM_ITERS 12
#define STG_B      32768
#define OFF_B      16384
#define GSM_TOTAL  (3 * STG_B)               // 96 KB

__device__ __forceinline__ void g_load_stage(int it, int stg, int m0, int n0,
                                             int tid, uint32_t smem_base) {
    const int kc = it * 64;
    const int row = tid >> 1;
    const int cb  = (tid & 1) * 4;
    const uint32_t sbase = smem_base + stg * STG_B;
    const __half* ah = d_Ah + (size_t)(m0 + row) * GTOT + kc;
    const __half* bw = d_Wh + (size_t)(n0 + row) * GTOT + kc;
    #pragma unroll
    for (int c = 0; c < 4; c++) {
        int ck = cb + c;
        uint32_t sw = row * 128 + ((ck ^ (row & 7)) << 4);
        CP_ASYNC16(sbase + sw,          ah + ck * 8);
        CP_ASYNC16(sbase + OFF_B + sw,  bw + ck * 8);
    }
}

__global__ void __launch_bounds__(256, 2)
k_logits(const float* __restrict__ bias, float* __restrict__ out)
{
    extern __shared__ char smem[];
    const uint32_t smem_base = smem_to_u32(smem);
    const int tid  = threadIdx.x;
    const int lane = tid & 31;
    const int wid  = tid >> 5;
    const int wm   = wid >> 1;
    const int wn   = wid & 1;
    const int m0 = blockIdx.y * 128;
    const int n0 = blockIdx.x * 128;

    float acc[2][8][4];
    #pragma unroll
    for (int mt = 0; mt < 2; mt++)
        #pragma unroll
        for (int nt = 0; nt < 8; nt++)
            #pragma unroll
            for (int q = 0; q < 4; q++) acc[mt][nt][q] = 0.f;

    const int lr  = lane & 15;
    const int lk8 = lane >> 4;

    g_load_stage(0, 0, m0, n0, tid, smem_base);
    CP_COMMIT();
    g_load_stage(1, 1, m0, n0, tid, smem_base);
    CP_COMMIT();

    for (int it = 0; it < GEMM_ITERS; it++) {
        CP_WAIT(1);
        __syncthreads();

        if (it + 2 < GEMM_ITERS) {
            g_load_stage(it + 2, (it + 2) % 3, m0, n0, tid, smem_base);
            CP_COMMIT();
        }

        const uint32_t sbase = smem_base + (it % 3) * STG_B;
        #pragma unroll
        for (int ks = 0; ks < 4; ks++) {
            const int k8 = ks * 2 + lk8;
            uint32_t afr[2][4], bfr[4][4];
            #pragma unroll
            for (int mt = 0; mt < 2; mt++) {
                int row = wm * 32 + mt * 16 + lr;
                uint32_t ad = sbase + row * 128 + ((k8 ^ (row & 7)) << 4);
                LDSM_X4(afr[mt][0], afr[mt][1], afr[mt][2], afr[mt][3], ad);
            }
            #pragma unroll
            for (int np = 0; np < 4; np++) {
                int rn = wn * 64 + np * 16 + lr;
                uint32_t bd = sbase + OFF_B + rn * 128 + ((k8 ^ (rn & 7)) << 4);
                LDSM_X4(bfr[np][0], bfr[np][1], bfr[np][2], bfr[np][3], bd);
            }
            #pragma unroll
            for (int mt = 0; mt < 2; mt++)
                #pragma unroll
                for (int np = 0; np < 4; np++) {
                    MMA16816(acc[mt][2 * np],     afr[mt], bfr[np][0], bfr[np][2]);
                    MMA16816(acc[mt][2 * np + 1], afr[mt], bfr[np][1], bfr[np][3]);
                }
        }
    }

    const int cq = 2 * (lane & 3);
    float2 bv[8];
    #pragma unroll
    for (int nt = 0; nt < 8; nt++)
        bv[nt] = *(const float2*)(bias + n0 + wn * 64 + nt * 8 + cq);

    #pragma unroll
    for (int mt = 0; mt < 2; mt++) {
        int rg = m0 + wm * 32 + mt * 16 + (lane >> 2);
        #pragma unroll
        for (int nt = 0; nt < 8; nt++) {
            float* p = out + (size_t)rg * NSTATES + n0 + wn * 64 + nt * 8 + cq;
            float2 v0 = make_float2(acc[mt][nt][0] + bv[nt].x, acc[mt][nt][1] + bv[nt].y);
            float2 v1 = make_float2(acc[mt][nt][2] + bv[nt].x, acc[mt][nt][3] + bv[nt].y);
            *(float2*)p = v0;
            *(float2*)(p + (size_t)8 * NSTATES) = v1;
        }
    }
}

// ---------------- launch -----------------------------------------------------
extern "C" void kernel_launch(void* const* d_in, const int* in_sizes, int n_in,
                              void* d_out, int out_size)
{
    const int *csi, *ai;
    const float *emb, *W, *bias, *D0, *D1, *D2, *D3;
    if (in_sizes[4] == NSTATES) {
        csi = (const int*)d_in[0]; ai = (const int*)d_in[1];
        emb = (const float*)d_in[2]; W = (const float*)d_in[3];
        bias = (const float*)d_in[4];
        D0 = (const float*)d_in[5]; D1 = (const float*)d_in[6];
        D2 = (const float*)d_in[7]; D3 = (const float*)d_in[8];
    } else {
        csi = (const int*)d_in[0]; ai = (const int*)d_in[1];
        emb = (const float*)d_in[2];
        D0 = (const float*)d_in[3]; D1 = (const float*)d_in[4];
        D2 = (const float*)d_in[5]; D3 = (const float*)d_in[6];
        W = (const float*)d_in[7]; bias = (const float*)d_in[8];
    }

    float* out = (float*)d_out;
    float* gout;
    if ((long long)out_size >= (long long)B_SZ * (NSTATES + GTOT)) {
        gout = out + (size_t)B_SZ * NSTATES;
    } else {
        cudaGetSymbolAddress((void**)&gout, d_gscratch);
    }

    k_sort<<<1, 1024>>>(ai);
    k_wsplit<<<(NSTATES * GTOT / 4) / 256, 256>>>(W);
    k_ehalf<<<(NSTATES * GTOT / 4) / 256, 256>>>(emb);
    dim3 dg(4 * 256 * 256 / 4 / 256, 1, 4);
    k_dhalf<<<dg, 256>>>(D0, D1, D2, D3);

    cudaFuncSetAttribute(k_transition, cudaFuncAttributeMaxDynamicSharedMemorySize, TSM_TOTAL);
    dim3 tg(128, 12, NACT);
    k_transition<<<tg, 256, TSM_TOTAL>>>(csi, emb, gout);

    cudaFuncSetAttribute(k_logits, cudaFuncAttributeMaxDynamicSharedMemorySize, GSM_TOTAL);
    dim3 gg(NSTATES / 128, B_SZ / 128);
    k_logits<<<gg, 256, GSM_TOTAL>>>(bias, out);
}